// round 1
// baseline (speedup 1.0000x reference)
#include <cuda_runtime.h>
#include <cuda_bf16.h>
#include <math.h>

// ---------------------------------------------------------------------------
// Problem constants
// ---------------------------------------------------------------------------
#define BATCH 512
#define MDIM  256       // M
#define NCOLS 512       // 2*M output columns per modality (x-proj | y-proj)
#define SPLITS 12       // split-K factor for the GEMM

// Scratch (device globals; no allocation allowed)
__device__ float g_P[3][BATCH][NCOLS];      // raw projections, 3 MB
__device__ float g_partial[3][2][BATCH];    // per-head partial dots

// ---------------------------------------------------------------------------
// Zero the atomic-accumulated projection scratch
// ---------------------------------------------------------------------------
__global__ void zero_kernel() {
    int i = blockIdx.x * blockDim.x + threadIdx.x;     // 768*256 = 196608 float4
    float4* p = reinterpret_cast<float4*>(&g_P[0][0][0]);
    p[i] = make_float4(0.f, 0.f, 0.f, 0.f);
}

// ---------------------------------------------------------------------------
// GEMM: C[b,n] = sum_k A[b,k] * W[n,k]   (both K-contiguous / "NT")
//   A: (512, K), Wx/Wy: (256, K) stacked into N=512, C: (512, 512)
//   Tile 128x128x8, 256 threads, 8x8 microtile, double-buffered smem,
//   split-K over blockIdx.z with atomicAdd epilogue.
// ---------------------------------------------------------------------------
__device__ __forceinline__ float4 ld4_guard(const float* p, int k0, int ke) {
    if (k0 + 4 <= ke) return *reinterpret_cast<const float4*>(p + k0);
    float4 v;
    v.x = (k0 + 0 < ke) ? p[k0 + 0] : 0.f;
    v.y = (k0 + 1 < ke) ? p[k0 + 1] : 0.f;
    v.z = (k0 + 2 < ke) ? p[k0 + 2] : 0.f;
    v.w = (k0 + 3 < ke) ? p[k0 + 3] : 0.f;
    return v;
}

__global__ __launch_bounds__(256)
void gemm_kernel(const float* __restrict__ A,
                 const float* __restrict__ Wx,
                 const float* __restrict__ Wy,
                 int K, int chunk, int modality)
{
    const int kb = blockIdx.z * chunk;
    if (kb >= K) return;
    const int ke = min(K, kb + chunk);

    const int row0 = blockIdx.x * 128;   // batch rows
    const int col0 = blockIdx.y * 128;   // output cols (0..255 = x-proj, 256..511 = y-proj)
    const float* Wbase = (col0 < 256) ? (Wx + (size_t)col0 * K)
                                      : (Wy + (size_t)(col0 - 256) * K);

    __shared__ float As[2][8][132];
    __shared__ float Ws[2][8][132];

    const int t   = threadIdx.x;
    const int r   = t >> 1;        // 0..127
    const int seg = t & 1;         // which half of the 8-wide K slab
    const int tx  = t & 15;        // microtile col group
    const int ty  = t >> 4;        // microtile row group

    const float* Ar = A     + (size_t)(row0 + r) * K;
    const float* Wr = Wbase + (size_t)r * K;

    float acc[8][8];
#pragma unroll
    for (int i = 0; i < 8; ++i)
#pragma unroll
        for (int j = 0; j < 8; ++j) acc[i][j] = 0.f;

    const int nIter = (ke - kb + 7) >> 3;

    // preload iter 0
    {
        float4 a = ld4_guard(Ar, kb + seg * 4, ke);
        float4 w = ld4_guard(Wr, kb + seg * 4, ke);
        As[0][seg*4+0][r] = a.x; As[0][seg*4+1][r] = a.y;
        As[0][seg*4+2][r] = a.z; As[0][seg*4+3][r] = a.w;
        Ws[0][seg*4+0][r] = w.x; Ws[0][seg*4+1][r] = w.y;
        Ws[0][seg*4+2][r] = w.z; Ws[0][seg*4+3][r] = w.w;
    }
    __syncthreads();

    for (int it = 0; it < nIter; ++it) {
        float4 a, w;
        const bool more = (it + 1 < nIter);
        if (more) {
            const int k0 = kb + (it + 1) * 8 + seg * 4;
            a = ld4_guard(Ar, k0, ke);
            w = ld4_guard(Wr, k0, ke);
        }
        const int buf = it & 1;
#pragma unroll
        for (int kk = 0; kk < 8; ++kk) {
            float af[8], bf[8];
            *reinterpret_cast<float4*>(&af[0]) = *reinterpret_cast<const float4*>(&As[buf][kk][ty*8]);
            *reinterpret_cast<float4*>(&af[4]) = *reinterpret_cast<const float4*>(&As[buf][kk][ty*8+4]);
            *reinterpret_cast<float4*>(&bf[0]) = *reinterpret_cast<const float4*>(&Ws[buf][kk][tx*8]);
            *reinterpret_cast<float4*>(&bf[4]) = *reinterpret_cast<const float4*>(&Ws[buf][kk][tx*8+4]);
#pragma unroll
            for (int i = 0; i < 8; ++i)
#pragma unroll
                for (int j = 0; j < 8; ++j)
                    acc[i][j] = fmaf(af[i], bf[j], acc[i][j]);
        }
        if (more) {
            const int nb = buf ^ 1;
            As[nb][seg*4+0][r] = a.x; As[nb][seg*4+1][r] = a.y;
            As[nb][seg*4+2][r] = a.z; As[nb][seg*4+3][r] = a.w;
            Ws[nb][seg*4+0][r] = w.x; Ws[nb][seg*4+1][r] = w.y;
            Ws[nb][seg*4+2][r] = w.z; Ws[nb][seg*4+3][r] = w.w;
        }
        __syncthreads();
    }

    float* C = &g_P[modality][0][0];
#pragma unroll
    for (int i = 0; i < 8; ++i) {
        const int row = row0 + ty * 8 + i;
#pragma unroll
        for (int j = 0; j < 8; ++j) {
            const int col = col0 + tx * 8 + j;
            atomicAdd(&C[row * NCOLS + col], acc[i][j]);
        }
    }
}

// ---------------------------------------------------------------------------
// Polynomial exp on [-1,1]: E entries are dots of unit 2-vectors.
// Degree-9 Taylor, rel err ~3e-7 on the interval. Runs on the FMA pipe
// (MUFU would bottleneck: 2e8 exps => ~1.4 ms).
// ---------------------------------------------------------------------------
__device__ __forceinline__ float expp(float x) {
    float r = 2.7557319e-6f;           // 1/9!
    r = fmaf(r, x, 2.4801587e-5f);     // 1/8!
    r = fmaf(r, x, 1.9841270e-4f);     // 1/7!
    r = fmaf(r, x, 1.3888889e-3f);     // 1/6!
    r = fmaf(r, x, 8.3333333e-3f);     // 1/5!
    r = fmaf(r, x, 4.1666668e-2f);     // 1/4!
    r = fmaf(r, x, 1.6666667e-1f);     // 1/3!
    r = fmaf(r, x, 0.5f);
    r = fmaf(r, x, 1.0f);
    r = fmaf(r, x, 1.0f);
    return r;
}

__device__ __forceinline__ float block_reduce_sum(float v, float* red) {
#pragma unroll
    for (int o = 16; o; o >>= 1) v += __shfl_xor_sync(0xffffffffu, v, o);
    const int t = threadIdx.x;
    __syncthreads();                    // protects red across repeated calls
    if ((t & 31) == 0) red[t >> 5] = v;
    __syncthreads();
    if (t == 0) {
        float s = 0.f;
#pragma unroll
        for (int i = 0; i < 8; ++i) s += red[i];
        v = s;
    }
    return v;                           // valid on thread 0
}

// ---------------------------------------------------------------------------
// Fused: normalize + energy + both softmax directions + attention-weighted
// features + partial head dots. One block per (batch, pair).
//   pair 0: (e,m) -> e_feat part0 / m_feat part0
//   pair 1: (e,c) -> e_feat part1 / c_feat part0
//   pair 2: (m,c) -> c_feat part1 (att_cm) / m_feat part1 (att_mc, row-normalized
//                    over the SUMMED index: needs rowsums, fused with loop 1)
// ---------------------------------------------------------------------------
__global__ __launch_bounds__(256)
void attn_kernel(const float* __restrict__ W3e,
                 const float* __restrict__ W3m,
                 const float* __restrict__ W3c)
{
    const int b    = blockIdx.x;
    const int pair = blockIdx.y;
    const int t    = threadIdx.x;

    __shared__ float sa[2 * MDIM];   // normalized a-matrix, interleaved (x,y)
    __shared__ float sb[2 * MDIM];   // normalized b-matrix
    __shared__ float rinv[MDIM];     // pair 2: 1/rowsum
    __shared__ float red[8];

    const int ai = (pair == 2) ? 1 : 0;          // e,e,m
    const int bi = (pair == 0) ? 1 : 2;          // m,c,c

    {
        const float* Pa = &g_P[ai][b][0];
        float px = Pa[t], py = Pa[MDIM + t];
        float inv = rsqrtf(px * px + py * py);
        sa[2 * t] = px * inv; sa[2 * t + 1] = py * inv;

        const float* Pb = &g_P[bi][b][0];
        px = Pb[t]; py = Pb[MDIM + t];
        inv = rsqrtf(px * px + py * py);
        sb[2 * t] = px * inv; sb[2 * t + 1] = py * inv;
    }
    __syncthreads();

    if (pair < 2) {
        // ---- Direction A: softmax over a-index (axis=1), output indexed by b-col t
        {
            const float bx = sb[2 * t], by = sb[2 * t + 1];
            float n0 = 0.f, n1 = 0.f, d = 0.f;
#pragma unroll 4
            for (int i = 0; i < MDIM; ++i) {
                const float ax = sa[2 * i], ay = sa[2 * i + 1];
                const float X = expp(fmaf(ay, by, ax * bx));
                d += X;
                n0 = fmaf(ax, X, n0);
                n1 = fmaf(ay, X, n1);
            }
            const float* WA = W3e + (pair == 0 ? 0 : 512);
            float v = (n0 * WA[t] + n1 * WA[MDIM + t]) / d;
            v = block_reduce_sum(v, red);
            if (t == 0) g_partial[0][pair][b] = v;   // head e, slot = pair
        }
        // ---- Direction B: softmax over b-index (axis=-1, transposed), output by a-col t
        {
            const float ax = sa[2 * t], ay = sa[2 * t + 1];
            float n0 = 0.f, n1 = 0.f, d = 0.f;
#pragma unroll 4
            for (int j = 0; j < MDIM; ++j) {
                const float bx = sb[2 * j], by = sb[2 * j + 1];
                const float X = expp(fmaf(ay, by, ax * bx));
                d += X;
                n0 = fmaf(bx, X, n0);
                n1 = fmaf(by, X, n1);
            }
            const float* WB = (pair == 0) ? W3m : W3c;   // part 0 of the b-head
            float v = (n0 * WB[t] + n1 * WB[MDIM + t]) / d;
            v = block_reduce_sum(v, red);
            if (t == 0) {
                if (pair == 0) g_partial[1][0][b] = v;   // head m slot 0
                else           g_partial[2][0][b] = v;   // head c slot 0
            }
        }
    } else {
        // ---- Loop 1: thread t = m-index. Produces att_cm output (c head part 1)
        //      and rowsum_t for att_mc.
        {
            const float ax = sa[2 * t], ay = sa[2 * t + 1];
            float n0 = 0.f, n1 = 0.f, d = 0.f;
#pragma unroll 4
            for (int j = 0; j < MDIM; ++j) {
                const float bx = sb[2 * j], by = sb[2 * j + 1];
                const float X = expp(fmaf(ay, by, ax * bx));
                d += X;
                n0 = fmaf(bx, X, n0);
                n1 = fmaf(by, X, n1);
            }
            const float id = 1.0f / d;
            rinv[t] = id;
            float v = (n0 * W3c[512 + t] + n1 * W3c[768 + t]) * id;
            v = block_reduce_sum(v, red);      // internal syncs also publish rinv
            if (t == 0) g_partial[2][1][b] = v;   // head c slot 1
        }
        // ---- Loop 2: thread t = c-index. att_mc: weights exp(E[i,t])/rowsum_i,
        //      NO per-output normalization (matches reference formula).
        {
            const float cx = sb[2 * t], cy = sb[2 * t + 1];
            float n0 = 0.f, n1 = 0.f;
#pragma unroll 4
            for (int i = 0; i < MDIM; ++i) {
                const float ax = sa[2 * i], ay = sa[2 * i + 1];
                const float X = expp(fmaf(ay, cy, ax * cx)) * rinv[i];
                n0 = fmaf(ax, X, n0);
                n1 = fmaf(ay, X, n1);
            }
            float v = n0 * W3m[512 + t] + n1 * W3m[768 + t];
            v = block_reduce_sum(v, red);
            if (t == 0) g_partial[1][1][b] = v;   // head m slot 1
        }
    }
}

// ---------------------------------------------------------------------------
// Final: sum the two partials per head, add bias, sigmoid.
// Output layout: [e(512) | m(512) | c(512)]
// ---------------------------------------------------------------------------
__global__ void final_kernel(const float* __restrict__ b3e,
                             const float* __restrict__ b3m,
                             const float* __restrict__ b3c,
                             float* __restrict__ out)
{
    const int b = blockIdx.x * blockDim.x + threadIdx.x;
    if (b >= BATCH) return;
    const float xe = g_partial[0][0][b] + g_partial[0][1][b] + b3e[0];
    const float xm = g_partial[1][0][b] + g_partial[1][1][b] + b3m[0];
    const float xc = g_partial[2][0][b] + g_partial[2][1][b] + b3c[0];
    out[b]             = 1.0f / (1.0f + expf(-xe));
    out[BATCH + b]     = 1.0f / (1.0f + expf(-xm));
    out[2 * BATCH + b] = 1.0f / (1.0f + expf(-xc));
}

// ---------------------------------------------------------------------------
// Launch
// ---------------------------------------------------------------------------
static inline int split_chunk(int K) {
    int c = (K + SPLITS - 1) / SPLITS;
    return (c + 7) & ~7;                 // multiple of 8 (BK) and of 4 (float4 align)
}

extern "C" void kernel_launch(void* const* d_in, const int* in_sizes, int n_in,
                              void* d_out, int out_size)
{
    const float* expr = (const float*)d_in[0];
    const float* mut  = (const float*)d_in[1];
    const float* cna  = (const float*)d_in[2];
    const float* Wex  = (const float*)d_in[3];
    const float* Wey  = (const float*)d_in[4];
    const float* Wmx  = (const float*)d_in[5];
    const float* Wmy  = (const float*)d_in[6];
    const float* Wcx  = (const float*)d_in[7];
    const float* Wcy  = (const float*)d_in[8];
    const float* W3e  = (const float*)d_in[9];
    const float* b3e  = (const float*)d_in[10];
    const float* W3m  = (const float*)d_in[11];
    const float* b3m  = (const float*)d_in[12];
    const float* W3c  = (const float*)d_in[13];
    const float* b3c  = (const float*)d_in[14];

    const int K1 = in_sizes[0] / BATCH;   // 20000
    const int K2 = in_sizes[1] / BATCH;   // 15000
    const int K3 = in_sizes[2] / BATCH;   // 20000

    zero_kernel<<<768, 256>>>();

    dim3 g(4, 4, SPLITS);
    gemm_kernel<<<g, 256>>>(expr, Wex, Wey, K1, split_chunk(K1), 0);
    gemm_kernel<<<g, 256>>>(mut,  Wmx, Wmy, K2, split_chunk(K2), 1);
    gemm_kernel<<<g, 256>>>(cna,  Wcx, Wcy, K3, split_chunk(K3), 2);

    attn_kernel<<<dim3(BATCH, 3), 256>>>(W3e, W3m, W3c);

    final_kernel<<<2, 256>>>(b3e, b3m, b3c, (float*)d_out);
}

// round 3
// speedup vs baseline: 2.7205x; 2.7205x over previous
#include <cuda_runtime.h>
#include <cuda_bf16.h>
#include <math.h>
#include <stdint.h>

#define BATCH 512
#define MDIM  256
#define NCOLS 512

#define BM 128
#define BN 128
#define BK 16
#define STG 3
#define LDA 20          // smem row stride in floats (conflict-free for frag loads)
#define SPLIT 4         // split-K factor

__device__ float g_P[3][BATCH][NCOLS];      // projections (atomic-accumulated)
__device__ float g_partial[3][2][BATCH];    // per-head partial dots

// ---------------------------------------------------------------------------
// helpers
// ---------------------------------------------------------------------------
__device__ __forceinline__ uint32_t smem_u32(const void* p) {
    uint32_t a;
    asm("{ .reg .u64 t; cvta.to.shared.u64 t, %1; cvt.u32.u64 %0, t; }" : "=r"(a) : "l"(p));
    return a;
}

__device__ __forceinline__ void cpa16(float* dst, const float* src, int nb) {
    asm volatile("cp.async.cg.shared.global [%0], [%1], 16, %2;"
                 :: "r"(smem_u32(dst)), "l"(src), "r"(nb) : "memory");
}

__device__ __forceinline__ void mma_tf32(float* d, const uint32_t* a, const uint32_t* b) {
    asm volatile(
        "mma.sync.aligned.m16n8k8.row.col.f32.tf32.tf32.f32 "
        "{%0,%1,%2,%3}, {%4,%5,%6,%7}, {%8,%9}, {%0,%1,%2,%3};"
        : "+f"(d[0]), "+f"(d[1]), "+f"(d[2]), "+f"(d[3])
        : "r"(a[0]), "r"(a[1]), "r"(a[2]), "r"(a[3]), "r"(b[0]), "r"(b[1]));
}

// ---------------------------------------------------------------------------
// zero projection scratch
// ---------------------------------------------------------------------------
__global__ void zero_kernel() {
    int i = blockIdx.x * blockDim.x + threadIdx.x;     // 768*256 float4
    float4* p = reinterpret_cast<float4*>(&g_P[0][0][0]);
    p[i] = make_float4(0.f, 0.f, 0.f, 0.f);
}

// ---------------------------------------------------------------------------
// stage loader: A tile 128x16, B tile 128x16 (B rows 0..255 = Wx, 256..511 = Wy)
// 16B cp.async chunks, zero-fill past K via src-size operand.
// ---------------------------------------------------------------------------
__device__ __forceinline__ void load_stage(
    const float* __restrict__ A, const float* __restrict__ Wx,
    const float* __restrict__ Wy, int K, int mt, int nt, int kt,
    float* As, float* Bs, int tid)
{
#pragma unroll
    for (int h = 0; h < 2; ++h) {
        const int ch  = tid + h * 256;      // 0..511
        const int row = ch >> 2, kc = ch & 3;
        const int k   = kt + kc * 4;
        int nb = (K - k) * 4; nb = nb < 0 ? 0 : (nb > 16 ? 16 : nb);
        const int ks = (k < K) ? k : 0;
        cpa16(As + row * LDA + kc * 4, A + (size_t)(mt * BM + row) * K + ks, nb);
    }
#pragma unroll
    for (int h = 0; h < 2; ++h) {
        const int ch  = tid + h * 256;
        const int row = ch >> 2, kc = ch & 3;
        const int n   = nt * BN + row;
        const float* base = (n < 256) ? (Wx + (size_t)n * K)
                                      : (Wy + (size_t)(n - 256) * K);
        const int k = kt + kc * 4;
        int nb = (K - k) * 4; nb = nb < 0 ? 0 : (nb > 16 ? 16 : nb);
        const int ks = (k < K) ? k : 0;
        cpa16(Bs + row * LDA + kc * 4, base + ks, nb);
    }
}

// ---------------------------------------------------------------------------
// tf32 mma.sync GEMM: C[128x128] tile, split-K, red.global.add epilogue.
// ---------------------------------------------------------------------------
__global__ __launch_bounds__(256, 2)
void gemm_mma(const float* __restrict__ e, const float* __restrict__ m,
              const float* __restrict__ c,
              const float* __restrict__ Wex, const float* __restrict__ Wey,
              const float* __restrict__ Wmx, const float* __restrict__ Wmy,
              const float* __restrict__ Wcx, const float* __restrict__ Wcy,
              int K0, int K1, int K2)
{
    const int mt  = blockIdx.x;
    const int nt  = blockIdx.y;
    const int mod = blockIdx.z / SPLIT;
    const int sp  = blockIdx.z % SPLIT;

    const float* A  = (mod == 0) ? e   : (mod == 1 ? m   : c);
    const float* Wx = (mod == 0) ? Wex : (mod == 1 ? Wmx : Wcx);
    const float* Wy = (mod == 0) ? Wey : (mod == 1 ? Wmy : Wcy);
    const int K     = (mod == 0) ? K0  : (mod == 1 ? K1  : K2);

    const int nk  = (K + BK - 1) / BK;
    const int per = (nk + SPLIT - 1) / SPLIT;
    const int i0  = sp * per;
    const int i1  = min(nk, i0 + per);
    if (i0 >= i1) return;
    const int n = i1 - i0;

    extern __shared__ float smf[];
    float* As = smf;                      // [STG][BM*LDA]
    float* Bs = smf + STG * BM * LDA;     // [STG][BN*LDA]

    const int tid  = threadIdx.x;
    const int lane = tid & 31;
    const int wid  = tid >> 5;
    const int wm   = (wid & 3) * 32;      // warp m-offset (4 warps down)
    const int wn   = (wid >> 2) * 64;     // warp n-offset (2 warps across)
    const int r    = lane >> 2;           // 0..7
    const int cq   = lane & 3;            // 0..3

    float acc[2][8][4];
#pragma unroll
    for (int i = 0; i < 2; ++i)
#pragma unroll
        for (int j = 0; j < 8; ++j)
#pragma unroll
            for (int q = 0; q < 4; ++q) acc[i][j][q] = 0.f;

    // prologue: stages i0, i0+1 -> slots 0, 1
    load_stage(A, Wx, Wy, K, mt, nt, (i0 + 0) * BK, As, Bs, tid);
    asm volatile("cp.async.commit_group;" ::: "memory");
    if (n > 1) load_stage(A, Wx, Wy, K, mt, nt, (i0 + 1) * BK,
                          As + 1 * BM * LDA, Bs + 1 * BN * LDA, tid);
    asm volatile("cp.async.commit_group;" ::: "memory");

    for (int it = 0; it < n; ++it) {
        asm volatile("cp.async.wait_group 1;" ::: "memory");
        __syncthreads();

        // issue loads for stage it+STG-1 into slot (it-1)%STG (safe: barrier above
        // separates from last iter's reads of that slot)
        if (it + STG - 1 < n) {
            const int ws = (it + STG - 1) % STG;
            load_stage(A, Wx, Wy, K, mt, nt, (i0 + it + STG - 1) * BK,
                       As + ws * BM * LDA, Bs + ws * BN * LDA, tid);
        }
        asm volatile("cp.async.commit_group;" ::: "memory");   // possibly empty group

        const int s = it % STG;
        const float* Ab = As + s * BM * LDA;
        const float* Bb = Bs + s * BN * LDA;

#pragma unroll
        for (int ks = 0; ks < 2; ++ks) {
            const int kb = ks * 8;
            uint32_t af[2][4], bf[8][2];
#pragma unroll
            for (int mi = 0; mi < 2; ++mi) {
                const float* ap = Ab + (wm + mi * 16 + r) * LDA + kb + cq;
                af[mi][0] = __float_as_uint(ap[0]);
                af[mi][1] = __float_as_uint(ap[8 * LDA]);
                af[mi][2] = __float_as_uint(ap[4]);
                af[mi][3] = __float_as_uint(ap[8 * LDA + 4]);
            }
#pragma unroll
            for (int ni = 0; ni < 8; ++ni) {
                const float* bp = Bb + (wn + ni * 8 + r) * LDA + kb + cq;
                bf[ni][0] = __float_as_uint(bp[0]);
                bf[ni][1] = __float_as_uint(bp[4]);
            }
#pragma unroll
            for (int mi = 0; mi < 2; ++mi)
#pragma unroll
                for (int ni = 0; ni < 8; ++ni)
                    mma_tf32(acc[mi][ni], af[mi], bf[ni]);
        }
    }

    // epilogue: atomic reduce into g_P
    float* Cb = &g_P[mod][0][0];
#pragma unroll
    for (int mi = 0; mi < 2; ++mi) {
        const int row = mt * BM + wm + mi * 16 + r;
#pragma unroll
        for (int ni = 0; ni < 8; ++ni) {
            const int col = nt * BN + wn + ni * 8 + cq * 2;
            float* p0 = Cb + (size_t)row * NCOLS + col;
            float* p1 = p0 + 8 * NCOLS;
            asm volatile("red.global.add.v2.f32 [%0], {%1, %2};"
                         :: "l"(p0), "f"(acc[mi][ni][0]), "f"(acc[mi][ni][1]) : "memory");
            asm volatile("red.global.add.v2.f32 [%0], {%1, %2};"
                         :: "l"(p1), "f"(acc[mi][ni][2]), "f"(acc[mi][ni][3]) : "memory");
        }
    }
}

// ---------------------------------------------------------------------------
// Polynomial exp on [-1,1] (E entries are dots of unit 2-vectors)
// ---------------------------------------------------------------------------
__device__ __forceinline__ float expp(float x) {
    float r = 2.7557319e-6f;
    r = fmaf(r, x, 2.4801587e-5f);
    r = fmaf(r, x, 1.9841270e-4f);
    r = fmaf(r, x, 1.3888889e-3f);
    r = fmaf(r, x, 8.3333333e-3f);
    r = fmaf(r, x, 4.1666668e-2f);
    r = fmaf(r, x, 1.6666667e-1f);
    r = fmaf(r, x, 0.5f);
    r = fmaf(r, x, 1.0f);
    r = fmaf(r, x, 1.0f);
    return r;
}

__device__ __forceinline__ float block_reduce_sum(float v, float* red) {
#pragma unroll
    for (int o = 16; o; o >>= 1) v += __shfl_xor_sync(0xffffffffu, v, o);
    const int t = threadIdx.x;
    __syncthreads();
    if ((t & 31) == 0) red[t >> 5] = v;
    __syncthreads();
    if (t == 0) {
        float s = 0.f;
#pragma unroll
        for (int i = 0; i < 8; ++i) s += red[i];
        v = s;
    }
    return v;
}

// ---------------------------------------------------------------------------
// Fused attention stage
// ---------------------------------------------------------------------------
__global__ __launch_bounds__(256)
void attn_kernel(const float* __restrict__ W3e,
                 const float* __restrict__ W3m,
                 const float* __restrict__ W3c)
{
    const int b    = blockIdx.x;
    const int pair = blockIdx.y;
    const int t    = threadIdx.x;

    __shared__ float sa[2 * MDIM];
    __shared__ float sb[2 * MDIM];
    __shared__ float rinv[MDIM];
    __shared__ float red[8];

    const int ai = (pair == 2) ? 1 : 0;
    const int bi = (pair == 0) ? 1 : 2;

    {
        const float* Pa = &g_P[ai][b][0];
        float px = Pa[t], py = Pa[MDIM + t];
        float inv = rsqrtf(px * px + py * py);
        sa[2 * t] = px * inv; sa[2 * t + 1] = py * inv;

        const float* Pb = &g_P[bi][b][0];
        px = Pb[t]; py = Pb[MDIM + t];
        inv = rsqrtf(px * px + py * py);
        sb[2 * t] = px * inv; sb[2 * t + 1] = py * inv;
    }
    __syncthreads();

    if (pair < 2) {
        {
            const float bx = sb[2 * t], by = sb[2 * t + 1];
            float n0 = 0.f, n1 = 0.f, d = 0.f;
#pragma unroll 4
            for (int i = 0; i < MDIM; ++i) {
                const float ax = sa[2 * i], ay = sa[2 * i + 1];
                const float X = expp(fmaf(ay, by, ax * bx));
                d += X;
                n0 = fmaf(ax, X, n0);
                n1 = fmaf(ay, X, n1);
            }
            const float* WA = W3e + (pair == 0 ? 0 : 512);
            float v = (n0 * WA[t] + n1 * WA[MDIM + t]) / d;
            v = block_reduce_sum(v, red);
            if (t == 0) g_partial[0][pair][b] = v;
        }
        {
            const float ax = sa[2 * t], ay = sa[2 * t + 1];
            float n0 = 0.f, n1 = 0.f, d = 0.f;
#pragma unroll 4
            for (int j = 0; j < MDIM; ++j) {
                const float bx = sb[2 * j], by = sb[2 * j + 1];
                const float X = expp(fmaf(ay, by, ax * bx));
                d += X;
                n0 = fmaf(bx, X, n0);
                n1 = fmaf(by, X, n1);
            }
            const float* WB = (pair == 0) ? W3m : W3c;
            float v = (n0 * WB[t] + n1 * WB[MDIM + t]) / d;
            v = block_reduce_sum(v, red);
            if (t == 0) {
                if (pair == 0) g_partial[1][0][b] = v;
                else           g_partial[2][0][b] = v;
            }
        }
    } else {
        {
            const float ax = sa[2 * t], ay = sa[2 * t + 1];
            float n0 = 0.f, n1 = 0.f, d = 0.f;
#pragma unroll 4
            for (int j = 0; j < MDIM; ++j) {
                const float bx = sb[2 * j], by = sb[2 * j + 1];
                const float X = expp(fmaf(ay, by, ax * bx));
                d += X;
                n0 = fmaf(bx, X, n0);
                n1 = fmaf(by, X, n1);
            }
            const float id = 1.0f / d;
            rinv[t] = id;
            float v = (n0 * W3c[512 + t] + n1 * W3c[768 + t]) * id;
            v = block_reduce_sum(v, red);
            if (t == 0) g_partial[2][1][b] = v;
        }
        {
            const float cx = sb[2 * t], cy = sb[2 * t + 1];
            float n0 = 0.f, n1 = 0.f;
#pragma unroll 4
            for (int i = 0; i < MDIM; ++i) {
                const float ax = sa[2 * i], ay = sa[2 * i + 1];
                const float X = expp(fmaf(ay, cy, ax * cx)) * rinv[i];
                n0 = fmaf(ax, X, n0);
                n1 = fmaf(ay, X, n1);
            }
            float v = n0 * W3m[512 + t] + n1 * W3m[768 + t];
            v = block_reduce_sum(v, red);
            if (t == 0) g_partial[1][1][b] = v;
        }
    }
}

__global__ void final_kernel(const float* __restrict__ b3e,
                             const float* __restrict__ b3m,
                             const float* __restrict__ b3c,
                             float* __restrict__ out)
{
    const int b = blockIdx.x * blockDim.x + threadIdx.x;
    if (b >= BATCH) return;
    const float xe = g_partial[0][0][b] + g_partial[0][1][b] + b3e[0];
    const float xm = g_partial[1][0][b] + g_partial[1][1][b] + b3m[0];
    const float xc = g_partial[2][0][b] + g_partial[2][1][b] + b3c[0];
    out[b]             = 1.0f / (1.0f + expf(-xe));
    out[BATCH + b]     = 1.0f / (1.0f + expf(-xm));
    out[2 * BATCH + b] = 1.0f / (1.0f + expf(-xc));
}

// ---------------------------------------------------------------------------
// Launch
// ---------------------------------------------------------------------------
extern "C" void kernel_launch(void* const* d_in, const int* in_sizes, int n_in,
                              void* d_out, int out_size)
{
    const float* expr = (const float*)d_in[0];
    const float* mut  = (const float*)d_in[1];
    const float* cna  = (const float*)d_in[2];
    const float* Wex  = (const float*)d_in[3];
    const float* Wey  = (const float*)d_in[4];
    const float* Wmx  = (const float*)d_in[5];
    const float* Wmy  = (const float*)d_in[6];
    const float* Wcx  = (const float*)d_in[7];
    const float* Wcy  = (const float*)d_in[8];
    const float* W3e  = (const float*)d_in[9];
    const float* b3e  = (const float*)d_in[10];
    const float* W3m  = (const float*)d_in[11];
    const float* b3m  = (const float*)d_in[12];
    const float* W3c  = (const float*)d_in[13];
    const float* b3c  = (const float*)d_in[14];

    const int K1 = in_sizes[0] / BATCH;   // 20000
    const int K2 = in_sizes[1] / BATCH;   // 15000
    const int K3 = in_sizes[2] / BATCH;   // 20000

    const int SMEM = STG * (BM + BN) * LDA * 4;   // 61440 B
    static bool attr_set = false;
    if (!attr_set) {
        cudaFuncSetAttribute(gemm_mma, cudaFuncAttributeMaxDynamicSharedMemorySize, SMEM);
        attr_set = true;
    }

    zero_kernel<<<768, 256>>>();

    gemm_mma<<<dim3(4, 4, 3 * SPLIT), 256, SMEM>>>(
        expr, mut, cna, Wex, Wey, Wmx, Wmy, Wcx, Wcy, K1, K2, K3);

    attn_kernel<<<dim3(BATCH, 3), 256>>>(W3e, W3m, W3c);

    final_kernel<<<2, 256>>>(b3e, b3m, b3c, (float*)d_out);
}

// round 4
// speedup vs baseline: 4.0937x; 1.5048x over previous
#include <cuda_runtime.h>
#include <cuda_bf16.h>
#include <math.h>
#include <stdint.h>

#define BATCH 512
#define MDIM  256
#define NCOLS 512

#define BM 128
#define BN 256
#define BK 16
#define STG 4
#define LDA 20          // smem row stride in floats (conflict-free fragment loads)
#define SPLIT 18        // split-K CTAs per modality -> 4*2*18 = 144 CTAs

#define LOG2E 1.4426950408889634f
#define LN2   0.6931471805599453f

__device__ float g_P[3][BATCH][NCOLS];      // projections (atomic-accumulated)
__device__ float g_partial[3][2][BATCH];    // per-head partial dots

// ---------------------------------------------------------------------------
// helpers
// ---------------------------------------------------------------------------
__device__ __forceinline__ uint32_t smem_u32(const void* p) {
    uint32_t a;
    asm("{ .reg .u64 t; cvta.to.shared.u64 t, %1; cvt.u32.u64 %0, t; }" : "=r"(a) : "l"(p));
    return a;
}
__device__ __forceinline__ void cpa16(float* dst, const float* src, int nb) {
    asm volatile("cp.async.cg.shared.global [%0], [%1], 16, %2;"
                 :: "r"(smem_u32(dst)), "l"(src), "r"(nb) : "memory");
}
__device__ __forceinline__ void mma_tf32(float* d, const uint32_t* a, const uint32_t* b) {
    asm volatile(
        "mma.sync.aligned.m16n8k8.row.col.f32.tf32.tf32.f32 "
        "{%0,%1,%2,%3}, {%4,%5,%6,%7}, {%8,%9}, {%0,%1,%2,%3};"
        : "+f"(d[0]), "+f"(d[1]), "+f"(d[2]), "+f"(d[3])
        : "r"(a[0]), "r"(a[1]), "r"(a[2]), "r"(a[3]), "r"(b[0]), "r"(b[1]));
}
__device__ __forceinline__ float ex2f(float x) {
    float y; asm("ex2.approx.f32 %0, %1;" : "=f"(y) : "f"(x)); return y;
}

// ---------------------------------------------------------------------------
// zero projection scratch
// ---------------------------------------------------------------------------
__global__ void zero_kernel() {
    int i = blockIdx.x * blockDim.x + threadIdx.x;     // 768*256 float4
    float4* p = reinterpret_cast<float4*>(&g_P[0][0][0]);
    p[i] = make_float4(0.f, 0.f, 0.f, 0.f);
}

// ---------------------------------------------------------------------------
// stage loader: A tile 128x16, B tile 256x16 (one W matrix: Wx if nt=0, Wy if nt=1)
// ---------------------------------------------------------------------------
__device__ __forceinline__ void load_stage(
    const float* __restrict__ A, const float* __restrict__ W,
    int K, int mt, int kt, float* As, float* Bs, int tid)
{
#pragma unroll
    for (int h = 0; h < 2; ++h) {                 // 512 A chunks
        const int ch = tid + h * 256;
        const int row = ch >> 2, kc = ch & 3;
        const int k = kt + kc * 4;
        int nb = (K - k) * 4; nb = nb < 0 ? 0 : (nb > 16 ? 16 : nb);
        const int ks = (k < K) ? k : 0;
        cpa16(As + row * LDA + kc * 4, A + (size_t)(mt * BM + row) * K + ks, nb);
    }
#pragma unroll
    for (int h = 0; h < 4; ++h) {                 // 1024 B chunks
        const int ch = tid + h * 256;
        const int row = ch >> 2, kc = ch & 3;
        const int k = kt + kc * 4;
        int nb = (K - k) * 4; nb = nb < 0 ? 0 : (nb > 16 ? 16 : nb);
        const int ks = (k < K) ? k : 0;
        cpa16(Bs + row * LDA + kc * 4, W + (size_t)row * K + ks, nb);
    }
}

// ---------------------------------------------------------------------------
// tf32 mma.sync GEMM, 128x256 CTA tile, phase loop over the 3 modalities so
// the L2 working set is one modality (~80MB < 126MB) at a time.
// ---------------------------------------------------------------------------
__global__ __launch_bounds__(256, 1)
void gemm_mma(const float* __restrict__ e, const float* __restrict__ m,
              const float* __restrict__ c,
              const float* __restrict__ Wex, const float* __restrict__ Wey,
              const float* __restrict__ Wmx, const float* __restrict__ Wmy,
              const float* __restrict__ Wcx, const float* __restrict__ Wcy,
              int K0, int K1, int K2)
{
    const int mt = blockIdx.x;          // batch tile (0..3)
    const int nt = blockIdx.y;          // 0 -> Wx half, 1 -> Wy half
    const int sp = blockIdx.z;          // split-K id

    extern __shared__ float smf[];
    float* As = smf;                          // [STG][BM*LDA]
    float* Bs = smf + STG * BM * LDA;         // [STG][BN*LDA]

    const int tid  = threadIdx.x;
    const int lane = tid & 31;
    const int wid  = tid >> 5;
    const int wm   = (wid & 1) * 64;          // warp grid 2(m) x 4(n)
    const int wn   = (wid >> 1) * 64;
    const int r    = lane >> 2;               // 0..7
    const int cq   = lane & 3;                // 0..3

#pragma unroll 1
    for (int mod = 0; mod < 3; ++mod) {
        const float* A = (mod == 0) ? e : (mod == 1 ? m : c);
        const float* W;
        if (mod == 0) W = nt ? Wey : Wex;
        else if (mod == 1) W = nt ? Wmy : Wmx;
        else W = nt ? Wcy : Wcx;
        const int K = (mod == 0) ? K0 : (mod == 1 ? K1 : K2);

        const int nk  = (K + BK - 1) / BK;
        const int per = (nk + SPLIT - 1) / SPLIT;
        const int i0  = sp * per;
        const int i1  = min(nk, i0 + per);
        const int n   = i1 - i0;
        if (n <= 0) { __syncthreads(); continue; }

        float acc[4][8][4];
#pragma unroll
        for (int a = 0; a < 4; ++a)
#pragma unroll
            for (int b = 0; b < 8; ++b)
#pragma unroll
                for (int q = 0; q < 4; ++q) acc[a][b][q] = 0.f;

        // prologue: stages 0..2
#pragma unroll
        for (int s = 0; s < STG - 1; ++s) {
            if (s < n) load_stage(A, W, K, mt, (i0 + s) * BK,
                                  As + s * BM * LDA, Bs + s * BN * LDA, tid);
            asm volatile("cp.async.commit_group;" ::: "memory");
        }

#pragma unroll 1
        for (int it = 0; it < n; ++it) {
            asm volatile("cp.async.wait_group %0;" :: "n"(STG - 2) : "memory");
            __syncthreads();

            if (it + STG - 1 < n) {
                const int ws = (it + STG - 1) % STG;
                load_stage(A, W, K, mt, (i0 + it + STG - 1) * BK,
                           As + ws * BM * LDA, Bs + ws * BN * LDA, tid);
            }
            asm volatile("cp.async.commit_group;" ::: "memory");

            const int s = it % STG;
            const float* Ab = As + s * BM * LDA;
            const float* Bb = Bs + s * BN * LDA;

#pragma unroll
            for (int ks = 0; ks < 2; ++ks) {
                const int kb = ks * 8;
                uint32_t af[4][4], bf[8][2];
#pragma unroll
                for (int mi = 0; mi < 4; ++mi) {
                    const float* ap = Ab + (wm + mi * 16 + r) * LDA + kb + cq;
                    af[mi][0] = __float_as_uint(ap[0]);
                    af[mi][1] = __float_as_uint(ap[8 * LDA]);
                    af[mi][2] = __float_as_uint(ap[4]);
                    af[mi][3] = __float_as_uint(ap[8 * LDA + 4]);
                }
#pragma unroll
                for (int ni = 0; ni < 8; ++ni) {
                    const float* bp = Bb + (wn + ni * 8 + r) * LDA + kb + cq;
                    bf[ni][0] = __float_as_uint(bp[0]);
                    bf[ni][1] = __float_as_uint(bp[4]);
                }
#pragma unroll
                for (int mi = 0; mi < 4; ++mi)
#pragma unroll
                    for (int ni = 0; ni < 8; ++ni)
                        mma_tf32(acc[mi][ni], af[mi], bf[ni]);
            }
        }

        asm volatile("cp.async.wait_group 0;" ::: "memory");
        __syncthreads();   // all compute done before next phase overwrites smem

        // epilogue: atomic reduce into g_P (cols nt*256 .. nt*256+255)
        float* Cb = &g_P[mod][0][0];
#pragma unroll
        for (int mi = 0; mi < 4; ++mi) {
            const int row = mt * BM + wm + mi * 16 + r;
#pragma unroll
            for (int ni = 0; ni < 8; ++ni) {
                const int col = nt * BN + wn + ni * 8 + cq * 2;
                float* p0 = Cb + (size_t)row * NCOLS + col;
                float* p1 = p0 + 8 * NCOLS;
                asm volatile("red.global.add.v2.f32 [%0], {%1, %2};"
                             :: "l"(p0), "f"(acc[mi][ni][0]), "f"(acc[mi][ni][1]) : "memory");
                asm volatile("red.global.add.v2.f32 [%0], {%1, %2};"
                             :: "l"(p1), "f"(acc[mi][ni][2]), "f"(acc[mi][ni][3]) : "memory");
            }
        }
    }
}

// ---------------------------------------------------------------------------
// block reduce (value valid on thread 0)
// ---------------------------------------------------------------------------
__device__ __forceinline__ float block_reduce_sum(float v, float* red) {
#pragma unroll
    for (int o = 16; o; o >>= 1) v += __shfl_xor_sync(0xffffffffu, v, o);
    const int t = threadIdx.x;
    __syncthreads();
    if ((t & 31) == 0) red[t >> 5] = v;
    __syncthreads();
    if (t == 0) {
        float s = 0.f;
#pragma unroll
        for (int i = 0; i < 8; ++i) s += red[i];
        v = s;
    }
    return v;
}

// ---------------------------------------------------------------------------
// Fused attention. exp via MUFU ex2 (parallel to FMA pipe). The a-side
// normalized vectors are pre-scaled by log2e (so the dot feeds ex2 directly);
// outputs weighted by the a-side get multiplied by ln2 once at the end.
// ---------------------------------------------------------------------------
__global__ __launch_bounds__(256)
void attn_kernel(const float* __restrict__ W3e,
                 const float* __restrict__ W3m,
                 const float* __restrict__ W3c)
{
    const int b    = blockIdx.x;
    const int pair = blockIdx.y;
    const int t    = threadIdx.x;

    __shared__ float2 sa[MDIM];   // a-side, scaled by LOG2E
    __shared__ float2 sb[MDIM];   // b-side, unscaled
    __shared__ float  rinv[MDIM];
    __shared__ float  red[8];

    const int ai = (pair == 2) ? 1 : 0;          // e,e,m
    const int bi = (pair == 0) ? 1 : 2;          // m,c,c

    {
        const float* Pa = &g_P[ai][b][0];
        float px = Pa[t], py = Pa[MDIM + t];
        float inv = rsqrtf(px * px + py * py) * LOG2E;
        sa[t] = make_float2(px * inv, py * inv);

        const float* Pb = &g_P[bi][b][0];
        px = Pb[t]; py = Pb[MDIM + t];
        inv = rsqrtf(px * px + py * py);
        sb[t] = make_float2(px * inv, py * inv);
    }
    __syncthreads();

    if (pair < 2) {
        // ---- Dir A: softmax over a-index; weights = a (scaled -> *LN2)
        {
            const float2 bv = sb[t];
            float n0 = 0.f, n1 = 0.f, d = 0.f;
#pragma unroll 4
            for (int i = 0; i < MDIM; ++i) {
                const float2 av = sa[i];
                const float X = ex2f(fmaf(av.y, bv.y, av.x * bv.x));
                d += X;
                n0 = fmaf(av.x, X, n0);
                n1 = fmaf(av.y, X, n1);
            }
            const float* WA = W3e + (pair == 0 ? 0 : 512);
            float v = LN2 * (n0 * WA[t] + n1 * WA[MDIM + t]) / d;
            v = block_reduce_sum(v, red);
            if (t == 0) g_partial[0][pair][b] = v;
        }
        // ---- Dir B: softmax over b-index; weights = b (unscaled)
        {
            const float2 av = sa[t];
            float n0 = 0.f, n1 = 0.f, d = 0.f;
#pragma unroll 4
            for (int j = 0; j < MDIM; ++j) {
                const float2 bv = sb[j];
                const float X = ex2f(fmaf(av.y, bv.y, av.x * bv.x));
                d += X;
                n0 = fmaf(bv.x, X, n0);
                n1 = fmaf(bv.y, X, n1);
            }
            const float* WB = (pair == 0) ? W3m : W3c;
            float v = (n0 * WB[t] + n1 * WB[MDIM + t]) / d;
            v = block_reduce_sum(v, red);
            if (t == 0) {
                if (pair == 0) g_partial[1][0][b] = v;
                else           g_partial[2][0][b] = v;
            }
        }
    } else {
        // ---- Loop 1: t = m-index; att_cm output (weights = c, unscaled) + rowsums
        {
            const float2 av = sa[t];
            float n0 = 0.f, n1 = 0.f, d = 0.f;
#pragma unroll 4
            for (int j = 0; j < MDIM; ++j) {
                const float2 bv = sb[j];
                const float X = ex2f(fmaf(av.y, bv.y, av.x * bv.x));
                d += X;
                n0 = fmaf(bv.x, X, n0);
                n1 = fmaf(bv.y, X, n1);
            }
            const float id = 1.0f / d;
            rinv[t] = id;
            float v = (n0 * W3c[512 + t] + n1 * W3c[768 + t]) * id;
            v = block_reduce_sum(v, red);     // internal syncs publish rinv
            if (t == 0) g_partial[2][1][b] = v;
        }
        // ---- Loop 2: t = c-index; att_mc (weights = m, scaled -> *LN2)
        {
            const float2 cv = sb[t];
            float n0 = 0.f, n1 = 0.f;
#pragma unroll 4
            for (int i = 0; i < MDIM; ++i) {
                const float2 av = sa[i];
                const float X = ex2f(fmaf(av.y, cv.y, av.x * cv.x)) * rinv[i];
                n0 = fmaf(av.x, X, n0);
                n1 = fmaf(av.y, X, n1);
            }
            float v = LN2 * (n0 * W3m[512 + t] + n1 * W3m[768 + t]);
            v = block_reduce_sum(v, red);
            if (t == 0) g_partial[1][1][b] = v;
        }
    }
}

__global__ void final_kernel(const float* __restrict__ b3e,
                             const float* __restrict__ b3m,
                             const float* __restrict__ b3c,
                             float* __restrict__ out)
{
    const int b = blockIdx.x * blockDim.x + threadIdx.x;
    if (b >= BATCH) return;
    const float xe = g_partial[0][0][b] + g_partial[0][1][b] + b3e[0];
    const float xm = g_partial[1][0][b] + g_partial[1][1][b] + b3m[0];
    const float xc = g_partial[2][0][b] + g_partial[2][1][b] + b3c[0];
    out[b]             = 1.0f / (1.0f + expf(-xe));
    out[BATCH + b]     = 1.0f / (1.0f + expf(-xm));
    out[2 * BATCH + b] = 1.0f / (1.0f + expf(-xc));
}

// ---------------------------------------------------------------------------
// Launch
// ---------------------------------------------------------------------------
extern "C" void kernel_launch(void* const* d_in, const int* in_sizes, int n_in,
                              void* d_out, int out_size)
{
    const float* expr = (const float*)d_in[0];
    const float* mut  = (const float*)d_in[1];
    const float* cna  = (const float*)d_in[2];
    const float* Wex  = (const float*)d_in[3];
    const float* Wey  = (const float*)d_in[4];
    const float* Wmx  = (const float*)d_in[5];
    const float* Wmy  = (const float*)d_in[6];
    const float* Wcx  = (const float*)d_in[7];
    const float* Wcy  = (const float*)d_in[8];
    const float* W3e  = (const float*)d_in[9];
    const float* b3e  = (const float*)d_in[10];
    const float* W3m  = (const float*)d_in[11];
    const float* b3m  = (const float*)d_in[12];
    const float* W3c  = (const float*)d_in[13];
    const float* b3c  = (const float*)d_in[14];

    const int K1 = in_sizes[0] / BATCH;   // 20000
    const int K2 = in_sizes[1] / BATCH;   // 15000
    const int K3 = in_sizes[2] / BATCH;   // 20000

    const int SMEM = STG * (BM + BN) * LDA * 4;   // 122880 B
    static bool attr_set = false;
    if (!attr_set) {
        cudaFuncSetAttribute(gemm_mma, cudaFuncAttributeMaxDynamicSharedMemorySize, SMEM);
        attr_set = true;
    }

    zero_kernel<<<768, 256>>>();

    gemm_mma<<<dim3(4, 2, SPLIT), 256, SMEM>>>(
        expr, mut, cna, Wex, Wey, Wmx, Wmy, Wcx, Wcy, K1, K2, K3);

    attn_kernel<<<dim3(BATCH, 3), 256>>>(W3e, W3m, W3c);

    final_kernel<<<2, 256>>>(b3e, b3m, b3c, (float*)d_out);
}

// round 6
// speedup vs baseline: 4.3769x; 1.0692x over previous
#include <cuda_runtime.h>
#include <cuda_bf16.h>
#include <math.h>
#include <stdint.h>

#define BATCH 512
#define MDIM  256
#define NCOLS 512

#define BM 128
#define BN 256
#define BK 16
#define STG 5
#define SPLIT 18        // split-K CTAs per modality -> 4*2*18 = 144 CTAs

#define AST (BM * BK)   // 2048 floats per A stage
#define BST (BN * BK)   // 4096 floats per B stage

#define LOG2E 1.4426950408889634f
#define LN2   0.6931471805599453f

__device__ float g_P[3][BATCH][NCOLS];      // projections (atomic-accumulated)
__device__ float g_partial[3][2][BATCH];    // per-head partial dots

// ---------------------------------------------------------------------------
// helpers
// ---------------------------------------------------------------------------
__device__ __forceinline__ uint32_t smem_u32(const void* p) {
    uint32_t a;
    asm("{ .reg .u64 t; cvta.to.shared.u64 t, %1; cvt.u32.u64 %0, t; }" : "=r"(a) : "l"(p));
    return a;
}
__device__ __forceinline__ void cpa16(float* dst, const float* src, int nb) {
    asm volatile("cp.async.cg.shared.global [%0], [%1], 16, %2;"
                 :: "r"(smem_u32(dst)), "l"(src), "r"(nb) : "memory");
}
__device__ __forceinline__ void mma_tf32(float* d, uint32_t a0, uint32_t a1,
                                         uint32_t a2, uint32_t a3,
                                         uint32_t b0, uint32_t b1) {
    asm volatile(
        "mma.sync.aligned.m16n8k8.row.col.f32.tf32.tf32.f32 "
        "{%0,%1,%2,%3}, {%4,%5,%6,%7}, {%8,%9}, {%0,%1,%2,%3};"
        : "+f"(d[0]), "+f"(d[1]), "+f"(d[2]), "+f"(d[3])
        : "r"(a0), "r"(a1), "r"(a2), "r"(a3), "r"(b0), "r"(b1));
}
__device__ __forceinline__ float ex2f(float x) {
    float y; asm("ex2.approx.f32 %0, %1;" : "=f"(y) : "f"(x)); return y;
}

// ---------------------------------------------------------------------------
// zero projection scratch
// ---------------------------------------------------------------------------
__global__ void zero_kernel() {
    int i = blockIdx.x * blockDim.x + threadIdx.x;     // 768*256 float4
    float4* p = reinterpret_cast<float4*>(&g_P[0][0][0]);
    p[i] = make_float4(0.f, 0.f, 0.f, 0.f);
}

// ---------------------------------------------------------------------------
// stage loader: A tile 128x16, B tile 256x16 (one W matrix), k-contiguous rows
// ---------------------------------------------------------------------------
__device__ __forceinline__ void load_stage(
    const float* __restrict__ A, const float* __restrict__ W,
    int K, int mt, int kt, float* As, float* Bs, int tid)
{
#pragma unroll
    for (int h = 0; h < 2; ++h) {                 // 512 A chunks of 16B
        const int ch = tid + h * 256;
        const int row = ch >> 2, kc = ch & 3;
        const int k = kt + kc * 4;
        int nb = (K - k) * 4; nb = nb < 0 ? 0 : (nb > 16 ? 16 : nb);
        const int ks = (k < K) ? k : 0;
        cpa16(As + row * BK + kc * 4, A + (size_t)(mt * BM + row) * K + ks, nb);
    }
#pragma unroll
    for (int h = 0; h < 4; ++h) {                 // 1024 B chunks
        const int ch = tid + h * 256;
        const int row = ch >> 2, kc = ch & 3;
        const int k = kt + kc * 4;
        int nb = (K - k) * 4; nb = nb < 0 ? 0 : (nb > 16 ? 16 : nb);
        const int ks = (k < K) ? k : 0;
        cpa16(Bs + row * BK + kc * 4, W + (size_t)row * K + ks, nb);
    }
}

// ---------------------------------------------------------------------------
// tf32 mma.sync GEMM, 128x256 CTA tile, phase loop over modalities.
// Fragment loads: one LDS.128 per 8x16 sub-tile per thread; the 4 loaded
// k-elements serve as mma columns (cq, cq+4) of k-steps 0 and 1 under a
// k-relabeling applied identically to A and B (sum is k-order invariant).
// ---------------------------------------------------------------------------
__global__ __launch_bounds__(256, 1)
void gemm_mma(const float* __restrict__ e, const float* __restrict__ m,
              const float* __restrict__ c,
              const float* __restrict__ Wex, const float* __restrict__ Wey,
              const float* __restrict__ Wmx, const float* __restrict__ Wmy,
              const float* __restrict__ Wcx, const float* __restrict__ Wcy,
              int K0, int K1, int K2)
{
    const int mt = blockIdx.x;          // batch tile (0..3)
    const int nt = blockIdx.y;          // 0 -> Wx half, 1 -> Wy half
    const int sp = blockIdx.z;          // split-K id

    extern __shared__ float smf[];
    float* As = smf;                          // [STG][AST]
    float* Bs = smf + STG * AST;              // [STG][BST]

    const int tid  = threadIdx.x;
    const int lane = tid & 31;
    const int wid  = tid >> 5;
    const int wm   = (wid & 1) * 64;          // warp grid 2(m) x 4(n)
    const int wn   = (wid >> 1) * 64;
    const int r    = lane >> 2;               // 0..7
    const int cq   = lane & 3;                // 0..3

#pragma unroll 1
    for (int mod = 0; mod < 3; ++mod) {
        const float* A = (mod == 0) ? e : (mod == 1 ? m : c);
        const float* W;
        if (mod == 0) W = nt ? Wey : Wex;
        else if (mod == 1) W = nt ? Wmy : Wmx;
        else W = nt ? Wcy : Wcx;
        const int K = (mod == 0) ? K0 : (mod == 1 ? K1 : K2);

        const int nk  = (K + BK - 1) / BK;
        const int per = (nk + SPLIT - 1) / SPLIT;
        const int i0  = sp * per;
        const int i1  = min(nk, i0 + per);
        const int n   = i1 - i0;
        if (n <= 0) { __syncthreads(); continue; }

        float acc[4][8][4];
#pragma unroll
        for (int a = 0; a < 4; ++a)
#pragma unroll
            for (int b = 0; b < 8; ++b)
#pragma unroll
                for (int q = 0; q < 4; ++q) acc[a][b][q] = 0.f;

        // prologue
#pragma unroll
        for (int s = 0; s < STG - 1; ++s) {
            if (s < n) load_stage(A, W, K, mt, (i0 + s) * BK,
                                  As + s * AST, Bs + s * BST, tid);
            asm volatile("cp.async.commit_group;" ::: "memory");
        }

#pragma unroll 1
        for (int it = 0; it < n; ++it) {
            asm volatile("cp.async.wait_group %0;" :: "n"(STG - 2) : "memory");
            __syncthreads();

            if (it + STG - 1 < n) {
                const int ws = (it + STG - 1) % STG;
                load_stage(A, W, K, mt, (i0 + it + STG - 1) * BK,
                           As + ws * AST, Bs + ws * BST, tid);
            }
            asm volatile("cp.async.commit_group;" ::: "memory");

            const int s = it % STG;
            const float* Ab = As + s * AST;
            const float* Bb = Bs + s * BST;

            // one LDS.128 per 8-row sub-tile: rows r / r+8, k-words 4cq..4cq+3
            uint4 alo[4], ahi[4], bv[8];
#pragma unroll
            for (int mi = 0; mi < 4; ++mi) {
                const float* ap = Ab + (wm + mi * 16 + r) * BK + cq * 4;
                alo[mi] = *reinterpret_cast<const uint4*>(ap);
                ahi[mi] = *reinterpret_cast<const uint4*>(ap + 8 * BK);
            }
#pragma unroll
            for (int ni = 0; ni < 8; ++ni) {
                const float* bp = Bb + (wn + ni * 8 + r) * BK + cq * 4;
                bv[ni] = *reinterpret_cast<const uint4*>(bp);
            }

            // k-step 0: elements (x, y) of each uint4; k-step 1: (z, w)
#pragma unroll
            for (int mi = 0; mi < 4; ++mi)
#pragma unroll
                for (int ni = 0; ni < 8; ++ni)
                    mma_tf32(acc[mi][ni], alo[mi].x, ahi[mi].x, alo[mi].y, ahi[mi].y,
                             bv[ni].x, bv[ni].y);
#pragma unroll
            for (int mi = 0; mi < 4; ++mi)
#pragma unroll
                for (int ni = 0; ni < 8; ++ni)
                    mma_tf32(acc[mi][ni], alo[mi].z, ahi[mi].z, alo[mi].w, ahi[mi].w,
                             bv[ni].z, bv[ni].w);
        }

        asm volatile("cp.async.wait_group 0;" ::: "memory");
        __syncthreads();   // all compute done before next phase overwrites smem

        // epilogue: atomic reduce into g_P (cols nt*256 .. nt*256+255)
        float* Cb = &g_P[mod][0][0];
#pragma unroll
        for (int mi = 0; mi < 4; ++mi) {
            const int row = mt * BM + wm + mi * 16 + r;
#pragma unroll
            for (int ni = 0; ni < 8; ++ni) {
                const int col = nt * BN + wn + ni * 8 + cq * 2;
                float* p0 = Cb + (size_t)row * NCOLS + col;
                float* p1 = p0 + 8 * NCOLS;
                asm volatile("red.global.add.v2.f32 [%0], {%1, %2};"
                             :: "l"(p0), "f"(acc[mi][ni][0]), "f"(acc[mi][ni][1]) : "memory");
                asm volatile("red.global.add.v2.f32 [%0], {%1, %2};"
                             :: "l"(p1), "f"(acc[mi][ni][2]), "f"(acc[mi][ni][3]) : "memory");
            }
        }
    }
}

// ---------------------------------------------------------------------------
// block reduce (value valid on thread 0)
// ---------------------------------------------------------------------------
__device__ __forceinline__ float block_reduce_sum(float v, float* red) {
#pragma unroll
    for (int o = 16; o; o >>= 1) v += __shfl_xor_sync(0xffffffffu, v, o);
    const int t = threadIdx.x;
    __syncthreads();
    if ((t & 31) == 0) red[t >> 5] = v;
    __syncthreads();
    if (t == 0) {
        float s = 0.f;
#pragma unroll
        for (int i = 0; i < 8; ++i) s += red[i];
        v = s;
    }
    return v;
}

// ---------------------------------------------------------------------------
// Fused attention. exp via MUFU ex2; a-side vectors pre-scaled by log2e.
// ---------------------------------------------------------------------------
__global__ __launch_bounds__(256)
void attn_kernel(const float* __restrict__ W3e,
                 const float* __restrict__ W3m,
                 const float* __restrict__ W3c)
{
    const int b    = blockIdx.x;
    const int pair = blockIdx.y;
    const int t    = threadIdx.x;

    __shared__ float2 sa[MDIM];   // a-side, scaled by LOG2E
    __shared__ float2 sb[MDIM];   // b-side, unscaled
    __shared__ float  rinv[MDIM];
    __shared__ float  red[8];

    const int ai = (pair == 2) ? 1 : 0;          // e,e,m
    const int bi = (pair == 0) ? 1 : 2;          // m,c,c

    {
        const float* Pa = &g_P[ai][b][0];
        float px = Pa[t], py = Pa[MDIM + t];
        float inv = rsqrtf(px * px + py * py) * LOG2E;
        sa[t] = make_float2(px * inv, py * inv);

        const float* Pb = &g_P[bi][b][0];
        px = Pb[t]; py = Pb[MDIM + t];
        inv = rsqrtf(px * px + py * py);
        sb[t] = make_float2(px * inv, py * inv);
    }
    __syncthreads();

    if (pair < 2) {
        {
            const float2 bv = sb[t];
            float n0 = 0.f, n1 = 0.f, d = 0.f;
#pragma unroll 8
            for (int i = 0; i < MDIM; ++i) {
                const float2 av = sa[i];
                const float X = ex2f(fmaf(av.y, bv.y, av.x * bv.x));
                d += X;
                n0 = fmaf(av.x, X, n0);
                n1 = fmaf(av.y, X, n1);
            }
            const float* WA = W3e + (pair == 0 ? 0 : 512);
            float v = LN2 * (n0 * WA[t] + n1 * WA[MDIM + t]) / d;
            v = block_reduce_sum(v, red);
            if (t == 0) g_partial[0][pair][b] = v;
        }
        {
            const float2 av = sa[t];
            float n0 = 0.f, n1 = 0.f, d = 0.f;
#pragma unroll 8
            for (int j = 0; j < MDIM; ++j) {
                const float2 bv = sb[j];
                const float X = ex2f(fmaf(av.y, bv.y, av.x * bv.x));
                d += X;
                n0 = fmaf(bv.x, X, n0);
                n1 = fmaf(bv.y, X, n1);
            }
            const float* WB = (pair == 0) ? W3m : W3c;
            float v = (n0 * WB[t] + n1 * WB[MDIM + t]) / d;
            v = block_reduce_sum(v, red);
            if (t == 0) {
                if (pair == 0) g_partial[1][0][b] = v;
                else           g_partial[2][0][b] = v;
            }
        }
    } else {
        {
            const float2 av = sa[t];
            float n0 = 0.f, n1 = 0.f, d = 0.f;
#pragma unroll 8
            for (int j = 0; j < MDIM; ++j) {
                const float2 bv = sb[j];
                const float X = ex2f(fmaf(av.y, bv.y, av.x * bv.x));
                d += X;
                n0 = fmaf(bv.x, X, n0);
                n1 = fmaf(bv.y, X, n1);
            }
            const float id = 1.0f / d;
            rinv[t] = id;
            float v = (n0 * W3c[512 + t] + n1 * W3c[768 + t]) * id;
            v = block_reduce_sum(v, red);     // internal syncs publish rinv
            if (t == 0) g_partial[2][1][b] = v;
        }
        {
            const float2 cv = sb[t];
            float n0 = 0.f, n1 = 0.f;
#pragma unroll 8
            for (int i = 0; i < MDIM; ++i) {
                const float2 av = sa[i];
                const float X = ex2f(fmaf(av.y, cv.y, av.x * cv.x)) * rinv[i];
                n0 = fmaf(av.x, X, n0);
                n1 = fmaf(av.y, X, n1);
            }
            float v = LN2 * (n0 * W3m[512 + t] + n1 * W3m[768 + t]);
            v = block_reduce_sum(v, red);
            if (t == 0) g_partial[1][1][b] = v;
        }
    }
}

__global__ void final_kernel(const float* __restrict__ b3e,
                             const float* __restrict__ b3m,
                             const float* __restrict__ b3c,
                             float* __restrict__ out)
{
    const int b = blockIdx.x * blockDim.x + threadIdx.x;
    if (b >= BATCH) return;
    const float xe = g_partial[0][0][b] + g_partial[0][1][b] + b3e[0];
    const float xm = g_partial[1][0][b] + g_partial[1][1][b] + b3m[0];
    const float xc = g_partial[2][0][b] + g_partial[2][1][b] + b3c[0];
    out[b]             = 1.0f / (1.0f + expf(-xe));
    out[BATCH + b]     = 1.0f / (1.0f + expf(-xm));
    out[2 * BATCH + b] = 1.0f / (1.0f + expf(-xc));
}

// ---------------------------------------------------------------------------
// Launch
// ---------------------------------------------------------------------------
extern "C" void kernel_launch(void* const* d_in, const int* in_sizes, int n_in,
                              void* d_out, int out_size)
{
    const float* expr = (const float*)d_in[0];
    const float* mut  = (const float*)d_in[1];
    const float* cna  = (const float*)d_in[2];
    const float* Wex  = (const float*)d_in[3];
    const float* Wey  = (const float*)d_in[4];
    const float* Wmx  = (const float*)d_in[5];
    const float* Wmy  = (const float*)d_in[6];
    const float* Wcx  = (const float*)d_in[7];
    const float* Wcy  = (const float*)d_in[8];
    const float* W3e  = (const float*)d_in[9];
    const float* b3e  = (const float*)d_in[10];
    const float* W3m  = (const float*)d_in[11];
    const float* b3m  = (const float*)d_in[12];
    const float* W3c  = (const float*)d_in[13];
    const float* b3c  = (const float*)d_in[14];

    const int K1 = in_sizes[0] / BATCH;   // 20000
    const int K2 = in_sizes[1] / BATCH;   // 15000
    const int K3 = in_sizes[2] / BATCH;   // 20000

    const int SMEM = STG * (AST + BST) * 4;   // 5 * 24KB = 122880 B
    static bool attr_set = false;
    if (!attr_set) {
        cudaFuncSetAttribute(gemm_mma, cudaFuncAttributeMaxDynamicSharedMemorySize, SMEM);
        attr_set = true;
    }

    zero_kernel<<<768, 256>>>();

    gemm_mma<<<dim3(4, 2, SPLIT), 256, SMEM>>>(
        expr, mut, cna, Wex, Wey, Wmx, Wmy, Wcx, Wcy, K1, K2, K3);

    attn_kernel<<<dim3(BATCH, 3), 256>>>(W3e, W3m, W3c);

    final_kernel<<<2, 256>>>(b3e, b3m, b3c, (float*)d_out);
}

// round 7
// speedup vs baseline: 5.2888x; 1.2083x over previous
#include <cuda_runtime.h>
#include <cuda_bf16.h>
#include <cuda_fp16.h>
#include <math.h>
#include <stdint.h>

#define BATCH 512
#define MDIM  256
#define NCOLS 512

#define BM 128
#define BN 256
#define BK 16
#define STG 5
#define SPLIT 18        // split-K CTAs per modality -> 4*2*18 = 144 CTAs

#define AST (BM * BK)   // 2048 floats per A stage
#define BST (BN * BK)   // 4096 floats per B stage

#define LOG2E 1.4426950408889634f
#define LN2   0.6931471805599453f

__device__ float g_P[3][BATCH][NCOLS];      // projections (atomic-accumulated)
__device__ float g_partial[3][2][BATCH];    // per-head partial dots

// ---------------------------------------------------------------------------
// helpers
// ---------------------------------------------------------------------------
__device__ __forceinline__ uint32_t smem_u32(const void* p) {
    uint32_t a;
    asm("{ .reg .u64 t; cvta.to.shared.u64 t, %1; cvt.u32.u64 %0, t; }" : "=r"(a) : "l"(p));
    return a;
}
__device__ __forceinline__ void cpa16(float* dst, const float* src, int nb) {
    asm volatile("cp.async.cg.shared.global [%0], [%1], 16, %2;"
                 :: "r"(smem_u32(dst)), "l"(src), "r"(nb) : "memory");
}
// pack two f32 into f16x2: low half = lo (lower k index), high half = hi
__device__ __forceinline__ uint32_t pk(uint32_t lo, uint32_t hi) {
    uint32_t d;
    asm("cvt.rn.f16x2.f32 %0, %1, %2;"
        : "=r"(d) : "f"(__uint_as_float(hi)), "f"(__uint_as_float(lo)));
    return d;
}
__device__ __forceinline__ void mma_f16(float* d, uint32_t a0, uint32_t a1,
                                        uint32_t a2, uint32_t a3,
                                        uint32_t b0, uint32_t b1) {
    asm volatile(
        "mma.sync.aligned.m16n8k16.row.col.f32.f16.f16.f32 "
        "{%0,%1,%2,%3}, {%4,%5,%6,%7}, {%8,%9}, {%0,%1,%2,%3};"
        : "+f"(d[0]), "+f"(d[1]), "+f"(d[2]), "+f"(d[3])
        : "r"(a0), "r"(a1), "r"(a2), "r"(a3), "r"(b0), "r"(b1));
}
__device__ __forceinline__ float ex2f(float x) {
    float y; asm("ex2.approx.f32 %0, %1;" : "=f"(y) : "f"(x)); return y;
}

// ---------------------------------------------------------------------------
// zero projection scratch
// ---------------------------------------------------------------------------
__global__ void zero_kernel() {
    int i = blockIdx.x * blockDim.x + threadIdx.x;     // 768*256 float4
    float4* p = reinterpret_cast<float4*>(&g_P[0][0][0]);
    p[i] = make_float4(0.f, 0.f, 0.f, 0.f);
}

// ---------------------------------------------------------------------------
// stage loader: A tile 128x16, B tile 256x16 (one W matrix), k-contiguous rows
// ---------------------------------------------------------------------------
__device__ __forceinline__ void load_stage(
    const float* __restrict__ A, const float* __restrict__ W,
    int K, int mt, int kt, float* As, float* Bs, int tid)
{
#pragma unroll
    for (int h = 0; h < 2; ++h) {                 // 512 A chunks of 16B
        const int ch = tid + h * 256;
        const int row = ch >> 2, kc = ch & 3;
        const int k = kt + kc * 4;
        int nb = (K - k) * 4; nb = nb < 0 ? 0 : (nb > 16 ? 16 : nb);
        const int ks = (k < K) ? k : 0;
        cpa16(As + row * BK + kc * 4, A + (size_t)(mt * BM + row) * K + ks, nb);
    }
#pragma unroll
    for (int h = 0; h < 4; ++h) {                 // 1024 B chunks
        const int ch = tid + h * 256;
        const int row = ch >> 2, kc = ch & 3;
        const int k = kt + kc * 4;
        int nb = (K - k) * 4; nb = nb < 0 ? 0 : (nb > 16 ? 16 : nb);
        const int ks = (k < K) ? k : 0;
        cpa16(Bs + row * BK + kc * 4, W + (size_t)row * K + ks, nb);
    }
}

// ---------------------------------------------------------------------------
// fp16 mma.sync GEMM (m16n8k16, fp32 accum), 128x256 CTA tile, phase loop
// over modalities. Fragments: one LDS.128 per 8x16 sub-tile per thread; the
// 4 loaded fp32 k-values are converted to f16x2 and serve as mma k-slots
// (2cq,2cq+1) and (2cq+8,2cq+9) under a k-relabeling applied identically to
// A and B (the GEMM sum is k-order invariant).
// ---------------------------------------------------------------------------
__global__ __launch_bounds__(256, 1)
void gemm_mma(const float* __restrict__ e, const float* __restrict__ m,
              const float* __restrict__ c,
              const float* __restrict__ Wex, const float* __restrict__ Wey,
              const float* __restrict__ Wmx, const float* __restrict__ Wmy,
              const float* __restrict__ Wcx, const float* __restrict__ Wcy,
              int K0, int K1, int K2)
{
    const int mt = blockIdx.x;          // batch tile (0..3)
    const int nt = blockIdx.y;          // 0 -> Wx half, 1 -> Wy half
    const int sp = blockIdx.z;          // split-K id

    extern __shared__ float smf[];
    float* As = smf;                          // [STG][AST]
    float* Bs = smf + STG * AST;              // [STG][BST]

    const int tid  = threadIdx.x;
    const int lane = tid & 31;
    const int wid  = tid >> 5;
    const int wm   = (wid & 1) * 64;          // warp grid 2(m) x 4(n)
    const int wn   = (wid >> 1) * 64;
    const int r    = lane >> 2;               // 0..7
    const int cq   = lane & 3;                // 0..3

#pragma unroll 1
    for (int mod = 0; mod < 3; ++mod) {
        const float* A = (mod == 0) ? e : (mod == 1 ? m : c);
        const float* W;
        if (mod == 0) W = nt ? Wey : Wex;
        else if (mod == 1) W = nt ? Wmy : Wmx;
        else W = nt ? Wcy : Wcx;
        const int K = (mod == 0) ? K0 : (mod == 1 ? K1 : K2);

        const int nk  = (K + BK - 1) / BK;
        const int per = (nk + SPLIT - 1) / SPLIT;
        const int i0  = sp * per;
        const int i1  = min(nk, i0 + per);
        const int n   = i1 - i0;
        if (n <= 0) { __syncthreads(); continue; }

        float acc[4][8][4];
#pragma unroll
        for (int a = 0; a < 4; ++a)
#pragma unroll
            for (int b = 0; b < 8; ++b)
#pragma unroll
                for (int q = 0; q < 4; ++q) acc[a][b][q] = 0.f;

        // prologue
#pragma unroll
        for (int s = 0; s < STG - 1; ++s) {
            if (s < n) load_stage(A, W, K, mt, (i0 + s) * BK,
                                  As + s * AST, Bs + s * BST, tid);
            asm volatile("cp.async.commit_group;" ::: "memory");
        }

#pragma unroll 1
        for (int it = 0; it < n; ++it) {
            asm volatile("cp.async.wait_group %0;" :: "n"(STG - 2) : "memory");
            __syncthreads();

            if (it + STG - 1 < n) {
                const int ws = (it + STG - 1) % STG;
                load_stage(A, W, K, mt, (i0 + it + STG - 1) * BK,
                           As + ws * AST, Bs + ws * BST, tid);
            }
            asm volatile("cp.async.commit_group;" ::: "memory");

            const int s = it % STG;
            const float* Ab = As + s * AST;
            const float* Bb = Bs + s * BST;

            // one LDS.128 per 8x16 sub-tile: rows r / r+8, k-words 4cq..4cq+3
            uint4 alo[4], ahi[4], bv[8];
#pragma unroll
            for (int mi = 0; mi < 4; ++mi) {
                const float* ap = Ab + (wm + mi * 16 + r) * BK + cq * 4;
                alo[mi] = *reinterpret_cast<const uint4*>(ap);
                ahi[mi] = *reinterpret_cast<const uint4*>(ap + 8 * BK);
            }
#pragma unroll
            for (int ni = 0; ni < 8; ++ni) {
                const float* bp = Bb + (wn + ni * 8 + r) * BK + cq * 4;
                bv[ni] = *reinterpret_cast<const uint4*>(bp);
            }

            // convert to f16x2 fragments
            uint32_t af[4][4], bf[8][2];
#pragma unroll
            for (int mi = 0; mi < 4; ++mi) {
                af[mi][0] = pk(alo[mi].x, alo[mi].y);   // row r,  slots 2cq,2cq+1
                af[mi][1] = pk(ahi[mi].x, ahi[mi].y);   // row r+8
                af[mi][2] = pk(alo[mi].z, alo[mi].w);   // row r,  slots 2cq+8,2cq+9
                af[mi][3] = pk(ahi[mi].z, ahi[mi].w);   // row r+8
            }
#pragma unroll
            for (int ni = 0; ni < 8; ++ni) {
                bf[ni][0] = pk(bv[ni].x, bv[ni].y);
                bf[ni][1] = pk(bv[ni].z, bv[ni].w);
            }

#pragma unroll
            for (int mi = 0; mi < 4; ++mi)
#pragma unroll
                for (int ni = 0; ni < 8; ++ni)
                    mma_f16(acc[mi][ni], af[mi][0], af[mi][1], af[mi][2], af[mi][3],
                            bf[ni][0], bf[ni][1]);
        }

        asm volatile("cp.async.wait_group 0;" ::: "memory");
        __syncthreads();   // all compute done before next phase overwrites smem

        // epilogue: atomic reduce into g_P (cols nt*256 .. nt*256+255)
        float* Cb = &g_P[mod][0][0];
#pragma unroll
        for (int mi = 0; mi < 4; ++mi) {
            const int row = mt * BM + wm + mi * 16 + r;
#pragma unroll
            for (int ni = 0; ni < 8; ++ni) {
                const int col = nt * BN + wn + ni * 8 + cq * 2;
                float* p0 = Cb + (size_t)row * NCOLS + col;
                float* p1 = p0 + 8 * NCOLS;
                asm volatile("red.global.add.v2.f32 [%0], {%1, %2};"
                             :: "l"(p0), "f"(acc[mi][ni][0]), "f"(acc[mi][ni][1]) : "memory");
                asm volatile("red.global.add.v2.f32 [%0], {%1, %2};"
                             :: "l"(p1), "f"(acc[mi][ni][2]), "f"(acc[mi][ni][3]) : "memory");
            }
        }
    }
}

// ---------------------------------------------------------------------------
// block reduce (value valid on thread 0)
// ---------------------------------------------------------------------------
__device__ __forceinline__ float block_reduce_sum(float v, float* red) {
#pragma unroll
    for (int o = 16; o; o >>= 1) v += __shfl_xor_sync(0xffffffffu, v, o);
    const int t = threadIdx.x;
    __syncthreads();
    if ((t & 31) == 0) red[t >> 5] = v;
    __syncthreads();
    if (t == 0) {
        float s = 0.f;
#pragma unroll
        for (int i = 0; i < 8; ++i) s += red[i];
        v = s;
    }
    return v;
}

// ---------------------------------------------------------------------------
// Fused attention. exp via MUFU ex2; a-side vectors pre-scaled by log2e.
// ---------------------------------------------------------------------------
__global__ __launch_bounds__(256)
void attn_kernel(const float* __restrict__ W3e,
                 const float* __restrict__ W3m,
                 const float* __restrict__ W3c)
{
    const int b    = blockIdx.x;
    const int pair = blockIdx.y;
    const int t    = threadIdx.x;

    __shared__ float2 sa[MDIM];   // a-side, scaled by LOG2E
    __shared__ float2 sb[MDIM];   // b-side, unscaled
    __shared__ float  rinv[MDIM];
    __shared__ float  red[8];

    const int ai = (pair == 2) ? 1 : 0;          // e,e,m
    const int bi = (pair == 0) ? 1 : 2;          // m,c,c

    {
        const float* Pa = &g_P[ai][b][0];
        float px = Pa[t], py = Pa[MDIM + t];
        float inv = rsqrtf(px * px + py * py) * LOG2E;
        sa[t] = make_float2(px * inv, py * inv);

        const float* Pb = &g_P[bi][b][0];
        px = Pb[t]; py = Pb[MDIM + t];
        inv = rsqrtf(px * px + py * py);
        sb[t] = make_float2(px * inv, py * inv);
    }
    __syncthreads();

    if (pair < 2) {
        {
            const float2 bv = sb[t];
            float n0 = 0.f, n1 = 0.f, d = 0.f;
#pragma unroll 8
            for (int i = 0; i < MDIM; ++i) {
                const float2 av = sa[i];
                const float X = ex2f(fmaf(av.y, bv.y, av.x * bv.x));
                d += X;
                n0 = fmaf(av.x, X, n0);
                n1 = fmaf(av.y, X, n1);
            }
            const float* WA = W3e + (pair == 0 ? 0 : 512);
            float v = LN2 * (n0 * WA[t] + n1 * WA[MDIM + t]) / d;
            v = block_reduce_sum(v, red);
            if (t == 0) g_partial[0][pair][b] = v;
        }
        {
            const float2 av = sa[t];
            float n0 = 0.f, n1 = 0.f, d = 0.f;
#pragma unroll 8
            for (int j = 0; j < MDIM; ++j) {
                const float2 bv = sb[j];
                const float X = ex2f(fmaf(av.y, bv.y, av.x * bv.x));
                d += X;
                n0 = fmaf(bv.x, X, n0);
                n1 = fmaf(bv.y, X, n1);
            }
            const float* WB = (pair == 0) ? W3m : W3c;
            float v = (n0 * WB[t] + n1 * WB[MDIM + t]) / d;
            v = block_reduce_sum(v, red);
            if (t == 0) {
                if (pair == 0) g_partial[1][0][b] = v;
                else           g_partial[2][0][b] = v;
            }
        }
    } else {
        {
            const float2 av = sa[t];
            float n0 = 0.f, n1 = 0.f, d = 0.f;
#pragma unroll 8
            for (int j = 0; j < MDIM; ++j) {
                const float2 bv = sb[j];
                const float X = ex2f(fmaf(av.y, bv.y, av.x * bv.x));
                d += X;
                n0 = fmaf(bv.x, X, n0);
                n1 = fmaf(bv.y, X, n1);
            }
            const float id = 1.0f / d;
            rinv[t] = id;
            float v = (n0 * W3c[512 + t] + n1 * W3c[768 + t]) * id;
            v = block_reduce_sum(v, red);     // internal syncs publish rinv
            if (t == 0) g_partial[2][1][b] = v;
        }
        {
            const float2 cv = sb[t];
            float n0 = 0.f, n1 = 0.f;
#pragma unroll 8
            for (int i = 0; i < MDIM; ++i) {
                const float2 av = sa[i];
                const float X = ex2f(fmaf(av.y, cv.y, av.x * cv.x)) * rinv[i];
                n0 = fmaf(av.x, X, n0);
                n1 = fmaf(av.y, X, n1);
            }
            float v = LN2 * (n0 * W3m[512 + t] + n1 * W3m[768 + t]);
            v = block_reduce_sum(v, red);
            if (t == 0) g_partial[1][1][b] = v;
        }
    }
}

__global__ void final_kernel(const float* __restrict__ b3e,
                             const float* __restrict__ b3m,
                             const float* __restrict__ b3c,
                             float* __restrict__ out)
{
    const int b = blockIdx.x * blockDim.x + threadIdx.x;
    if (b >= BATCH) return;
    const float xe = g_partial[0][0][b] + g_partial[0][1][b] + b3e[0];
    const float xm = g_partial[1][0][b] + g_partial[1][1][b] + b3m[0];
    const float xc = g_partial[2][0][b] + g_partial[2][1][b] + b3c[0];
    out[b]             = 1.0f / (1.0f + expf(-xe));
    out[BATCH + b]     = 1.0f / (1.0f + expf(-xm));
    out[2 * BATCH + b] = 1.0f / (1.0f + expf(-xc));
}

// ---------------------------------------------------------------------------
// Launch
// ---------------------------------------------------------------------------
extern "C" void kernel_launch(void* const* d_in, const int* in_sizes, int n_in,
                              void* d_out, int out_size)
{
    const float* expr = (const float*)d_in[0];
    const float* mut  = (const float*)d_in[1];
    const float* cna  = (const float*)d_in[2];
    const float* Wex  = (const float*)d_in[3];
    const float* Wey  = (const float*)d_in[4];
    const float* Wmx  = (const float*)d_in[5];
    const float* Wmy  = (const float*)d_in[6];
    const float* Wcx  = (const float*)d_in[7];
    const float* Wcy  = (const float*)d_in[8];
    const float* W3e  = (const float*)d_in[9];
    const float* b3e  = (const float*)d_in[10];
    const float* W3m  = (const float*)d_in[11];
    const float* b3m  = (const float*)d_in[12];
    const float* W3c  = (const float*)d_in[13];
    const float* b3c  = (const float*)d_in[14];

    const int K1 = in_sizes[0] / BATCH;   // 20000
    const int K2 = in_sizes[1] / BATCH;   // 15000
    const int K3 = in_sizes[2] / BATCH;   // 20000

    const int SMEM = STG * (AST + BST) * 4;   // 5 * 24KB = 122880 B
    static bool attr_set = false;
    if (!attr_set) {
        cudaFuncSetAttribute(gemm_mma, cudaFuncAttributeMaxDynamicSharedMemorySize, SMEM);
        attr_set = true;
    }

    zero_kernel<<<768, 256>>>();

    gemm_mma<<<dim3(4, 2, SPLIT), 256, SMEM>>>(
        expr, mut, cna, Wex, Wey, Wmx, Wmy, Wcx, Wcy, K1, K2, K3);

    attn_kernel<<<dim3(BATCH, 3), 256>>>(W3e, W3m, W3c);

    final_kernel<<<2, 256>>>(b3e, b3m, b3c, (float*)d_out);
}